// round 17
// baseline (speedup 1.0000x reference)
#include <cuda_runtime.h>

// GRAPE qubit evolution — FINAL KERNEL.
//
// Math: all 20 pulse steps rotate about the same Pauli-X generator, so they
// commute and compose exactly into ONE rotation:
//   Theta = sum(a_k) * DT/2,  U = cos(Theta) I - i sin(Theta) X
// The lax.scan collapses to 4 fused FMAs per column:
//   pair A: (r0, m1) -> out0r = c*r0 + s*m1 ; out1i = c*m1 - s*r0
//   pair B: (r1, m0) -> out1r = c*r1 + s*m0 ; out0i = c*m0 - s*r1
// rel_err vs the 20-step reference: 2.4e-7 (threshold 1e-3).
//
// Performance: pure 256 MiB stream (128 MiB read + 128 MiB write,
// irreducible). Measured optimum = 43.5us dur (x3 reproductions), kernel
// ~37us, DRAM ~74%, ~6.2 TB/s effective = GB300 mixed-R/W HBM roofline.
// Config: contiguous pair-split (each grid half owns an independent
// 2-read/2-write stream set), ILP=1, float4, __ldg loads, __stcs stores
// (skip L2 write-allocate churn), 256-thread blocks.
// Proven neutral-or-worse over 16 rounds: ILP=2 (two forms), 256-bit
// LDG/STG, __ldcs, L2 evict-priority hints (inert across graph replays),
// even/odd stream interleave, persistent single-wave grid, block sizes
// {128, 512, 1024}.

#define NUM_STEPS 20
#define DT_HALF   (0.5f * (1.0f / 20.0f))
#define BATCH     8388608

__global__ __launch_bounds__(256) void grape_kernel(
    const float* __restrict__ amps,
    const float* __restrict__ sr,
    const float* __restrict__ si,
    float* __restrict__ out)
{
    float theta = 0.0f;
#pragma unroll
    for (int k = 0; k < NUM_STEPS; k++) theta += __ldg(&amps[k]);
    theta *= DT_HALF;
    const float c = cosf(theta);
    const float s = sinf(theta);

    const int n4  = BATCH / 4;                 // 2,097,152 float4 per row
    const int tid = blockIdx.x * blockDim.x + threadIdx.x;

    if (tid < n4) {
        // ---- pair A: (r0, m1) -> out0r, out1i ----
        const int i = tid;
        const float4* sr0 = (const float4*)sr;
        const float4* si1 = (const float4*)(si + (size_t)BATCH);
        float4* out0r = (float4*)out;
        float4* out1i = (float4*)(out + 3 * (size_t)BATCH);

        float4 a = __ldg(&sr0[i]);   // r0
        float4 b = __ldg(&si1[i]);   // m1

        float4 o1, o2;
        o1.x = fmaf(c, a.x,  s * b.x);  o2.x = fmaf(c, b.x, -s * a.x);
        o1.y = fmaf(c, a.y,  s * b.y);  o2.y = fmaf(c, b.y, -s * a.y);
        o1.z = fmaf(c, a.z,  s * b.z);  o2.z = fmaf(c, b.z, -s * a.z);
        o1.w = fmaf(c, a.w,  s * b.w);  o2.w = fmaf(c, b.w, -s * a.w);

        __stcs(&out0r[i], o1);
        __stcs(&out1i[i], o2);
    } else {
        // ---- pair B: (r1, m0) -> out1r, out0i ----
        const int i = tid - n4;
        const float4* sr1 = (const float4*)(sr + (size_t)BATCH);
        const float4* si0 = (const float4*)si;
        float4* out1r = (float4*)(out + (size_t)BATCH);
        float4* out0i = (float4*)(out + 2 * (size_t)BATCH);

        float4 a = __ldg(&sr1[i]);   // r1
        float4 b = __ldg(&si0[i]);   // m0

        float4 o1, o2;
        o1.x = fmaf(c, a.x,  s * b.x);  o2.x = fmaf(c, b.x, -s * a.x);
        o1.y = fmaf(c, a.y,  s * b.y);  o2.y = fmaf(c, b.y, -s * a.y);
        o1.z = fmaf(c, a.z,  s * b.z);  o2.z = fmaf(c, b.z, -s * a.z);
        o1.w = fmaf(c, a.w,  s * b.w);  o2.w = fmaf(c, b.w, -s * a.w);

        __stcs(&out1r[i], o1);
        __stcs(&out0i[i], o2);
    }
}

extern "C" void kernel_launch(void* const* d_in, const int* in_sizes, int n_in,
                              void* d_out, int out_size)
{
    const float* amps = (const float*)d_in[0];  // [20]
    const float* sr   = (const float*)d_in[1];  // [2, B]
    const float* si   = (const float*)d_in[2];  // [2, B]
    float* out        = (float*)d_out;          // [2, 2, B]

    const int n4 = BATCH / 4;
    const int threads = 256;
    const int blocks = (2 * n4) / threads;      // 16384
    grape_kernel<<<blocks, threads>>>(amps, sr, si, out);
}